// round 6
// baseline (speedup 1.0000x reference)
#include <cuda_runtime.h>
#include <math.h>
#include <stdint.h>

// Problem constants (match reference setup_inputs)
#define DIMF     2048
#define KIDS     8
#define P        256
#define HALF     2048
#define MARGIN   1.0f

#define THREADS  256
#define GROUP    16                    // rows per identity (2*K)
#define CHUNK    512                   // K floats per chunk
#define NCHUNK   (DIMF / CHUNK)        // 4
#define NBUF     3                     // triple buffer -> 96 KB in flight/CTA
#define STRIDE_F 516                   // padded smem row stride (floats)
#define ROW_BYTES    (CHUNK * 4)       // 2048 B per row per chunk
#define STRIDE_BYTES (STRIDE_F * 4)    // 2064 (16B multiple)
#define BUF_FLOATS   (GROUP * STRIDE_F)
#define BUF_BYTES    (GROUP * STRIDE_BYTES)   // 33024
#define SMEM_BYTES   (NBUF * BUF_BYTES)       // 99072

// D(16x8) += A(16x8) * B(8x8), tf32. Gram trick: B fragments are A fragments.
#define MMA_TF32(d, a0, a1, a2, a3, b0, b1)                                \
    asm volatile(                                                          \
        "mma.sync.aligned.m16n8k8.row.col.f32.tf32.tf32.f32 "              \
        "{%0,%1,%2,%3}, {%4,%5,%6,%7}, {%8,%9}, {%0,%1,%2,%3};"            \
        : "+f"(d[0]), "+f"(d[1]), "+f"(d[2]), "+f"(d[3])                   \
        : "r"(a0), "r"(a1), "r"(a2), "r"(a3), "r"(b0), "r"(b1))

__device__ __forceinline__ uint32_t smem_u32(const void* p) {
    return (uint32_t)__cvta_generic_to_shared(p);
}
__device__ __forceinline__ void mbar_wait(uint32_t mbar, uint32_t parity) {
    asm volatile(
        "{\n\t.reg .pred P1;\n\t"
        "LAB_WAIT_%=:\n\t"
        "mbarrier.try_wait.parity.acquire.cta.shared::cta.b64 P1, [%0], %1, 0x989680;\n\t"
        "@P1 bra.uni LAB_DONE_%=;\n\t"
        "bra.uni LAB_WAIT_%=;\n\t"
        "LAB_DONE_%=:\n\t}"
        :: "r"(mbar), "r"(parity) : "memory");
}

__global__ __launch_bounds__(THREADS, 2)
void wloss_kernel(const float* __restrict__ x, float* __restrict__ out)
{
    extern __shared__ float smf[];               // [NBUF][16][STRIDE_F]
    __shared__ float    gram[GROUP][GROUP];
    __shared__ uint64_t s_mbar[NBUF];

    const int p    = blockIdx.x;                 // identity
    const int tid  = threadIdx.x;
    const int w    = tid >> 5;                   // warp 0..7 (K split)
    const int lane = tid & 31;

    const uint32_t smbase = smem_u32(smf);
    const uint32_t mbb    = smem_u32(&s_mbar[0]);

    if (tid < GROUP * GROUP)
        gram[tid >> 4][tid & 15] = 0.0f;
    if (tid == 0) {
        #pragma unroll
        for (int b = 0; b < NBUF; b++)
            asm volatile("mbarrier.init.shared.b64 [%0], 1;"
                         :: "r"(mbb + 8u * b) : "memory");
    }
    __syncthreads();

    // ---- bulk-async staging: 16 rows x 2KB per chunk, mbarrier-tracked ----
    auto stage = [&](int ch, int b) {
        uint32_t mb = mbb + 8u * b;
        asm volatile("mbarrier.arrive.expect_tx.shared.b64 _, [%0], %1;"
                     :: "r"(mb), "r"((uint32_t)(GROUP * ROW_BYTES)) : "memory");
        #pragma unroll
        for (int r = 0; r < GROUP; r++) {
            int grow = (r < KIDS) ? (p * KIDS + r)
                                  : (HALF + p * KIDS + (r - KIDS));
            const float* src = x + (size_t)grow * DIMF + ch * CHUNK;
            uint32_t dst = smbase + (uint32_t)(b * BUF_BYTES + r * STRIDE_BYTES);
            asm volatile(
                "cp.async.bulk.shared::cluster.global.mbarrier::complete_tx::bytes "
                "[%0], [%1], %2, [%3];"
                :: "r"(dst), "l"(src), "r"((uint32_t)ROW_BYTES), "r"(mb)
                : "memory");
        }
    };

    if (tid == 0) { stage(0, 0); stage(1, 1); stage(2, 2); }

    // ---- main loop: warp w handles K-slab [w*64, w*64+64) of each chunk ----
    float d1[4] = {0.f, 0.f, 0.f, 0.f};          // cols 0..7
    float d2[4] = {0.f, 0.f, 0.f, 0.f};          // cols 8..15
    const int fr = lane >> 2;                    // fragment row 0..7
    const int ft = lane & 3;                     // fragment k 0..3

    #pragma unroll
    for (int ch = 0; ch < NCHUNK; ch++) {
        const int b = ch % NBUF;
        mbar_wait(mbb + 8u * b, (uint32_t)((ch / NBUF) & 1));

        const float* buf = smf + b * BUF_FLOATS;
        const float* b0p = buf + fr * STRIDE_F + w * 64 + ft;
        const float* b1p = b0p + 8 * STRIDE_F;
        #pragma unroll
        for (int s = 0; s < 8; s++) {
            uint32_t a0 = __float_as_uint(b0p[s * 8]);
            uint32_t a2 = __float_as_uint(b0p[s * 8 + 4]);
            uint32_t a1 = __float_as_uint(b1p[s * 8]);
            uint32_t a3 = __float_as_uint(b1p[s * 8 + 4]);
            MMA_TF32(d1, a0, a1, a2, a3, a0, a2);   // B = rows 0..7
            MMA_TF32(d2, a0, a1, a2, a3, a1, a3);   // B = rows 8..15
        }
        if (ch + NBUF < NCHUNK) {
            __syncthreads();                     // all warps done with buffer b
            if (tid == 0) stage(ch + NBUF, b);
        }
    }

    // ---- reduce 8 warps' partial grams into smem ----
    {
        const int rr = lane >> 2;
        const int cc = 2 * (lane & 3);
        atomicAdd(&gram[rr][cc],         d1[0]);
        atomicAdd(&gram[rr][cc + 1],     d1[1]);
        atomicAdd(&gram[rr + 8][cc],     d1[2]);
        atomicAdd(&gram[rr + 8][cc + 1], d1[3]);
        atomicAdd(&gram[rr][8 + cc],         d2[0]);
        atomicAdd(&gram[rr][8 + cc + 1],     d2[1]);
        atomicAdd(&gram[rr + 8][8 + cc],     d2[2]);
        atomicAdd(&gram[rr + 8][8 + cc + 1], d2[3]);
    }
    __syncthreads();

    // ---- mins + loss (warp 0; diag of gram == squared norms) ----
    if (w == 0) {
        const int r = lane & 15;
        float inv = 1.0f / (sqrtf(gram[r][r]) + 1e-10f);
        float minf = INFINITY, mins = INFINITY;
        #pragma unroll
        for (int c = 0; c < GROUP; c++) {
            float invc = __shfl_sync(0xffffffffu, inv, c);
            float v = gram[r][c] * inv * invc;
            if (c < KIDS) minf = fminf(minf, v);
            else          mins = fminf(mins, v);
        }
        float li = fmaxf(MARGIN - minf, 0.0f) + fmaxf(MARGIN - mins, 0.0f);
        if (lane >= 16) li = 0.0f;
        #pragma unroll
        for (int o = 16; o; o >>= 1)
            li += __shfl_xor_sync(0xffffffffu, li, o);
        if (lane == 0)
            atomicAdd(out, li);
    }
}

extern "C" void kernel_launch(void* const* d_in, const int* in_sizes, int n_in,
                              void* d_out, int out_size)
{
    const float* x = (const float*)d_in[0];
    float* out = (float*)d_out;

    cudaMemsetAsync(out, 0, sizeof(float), 0);

    static bool attr_set = false;
    if (!attr_set) {
        cudaFuncSetAttribute(wloss_kernel,
                             cudaFuncAttributeMaxDynamicSharedMemorySize,
                             SMEM_BYTES);
        attr_set = true;
    }

    wloss_kernel<<<P, THREADS, SMEM_BYTES>>>(x, out);
}